// round 12
// baseline (speedup 1.0000x reference)
#include <cuda_runtime.h>
#include <cuda_fp16.h>
#include <math.h>
#include <stdint.h>

#define BATCH 32
#define TK    8192
#define H     256
#define NROWS (BATCH*TK)     // 262144
#define TM    64
#define NT    (NROWS/TM)     // 4096
#define NTHREADS 384         // 8 MMA warps + 4 converter warps

// scores SMEM layout (bytes)
#define SM_X   0              // 2 x 32768 (64 rows x 256 k fp16, swizzled)
#define SM_W   65536          // 131072 (256 g x 256 k fp16, swizzled)
#define SM_WC  196608         // 1024
#define SM_V   197632         // 1024
#define SMEM_TOTAL 198656     // 194 KB

// ---------------- device scratch ----------------
__device__ __half g_enc_h[(size_t)NROWS * H];   // fp16 copy (written by scores, read by ctx)
__device__ float  g_dec_fea[BATCH*H];
__device__ float  g_scores_p[4][NROWS];         // per-col-warp partial scores
__device__ float  g_ct_part[BATCH*32*H];

// ---------------- helpers ----------------
__device__ __forceinline__ uint32_t smem_u32(const void* p) {
    uint32_t a;
    asm("{ .reg .u64 t; cvta.to.shared.u64 t, %1; cvt.u32.u64 %0, t; }" : "=r"(a) : "l"(p));
    return a;
}
__device__ __forceinline__ float fast_tanh(float x) {
    float r; asm("tanh.approx.f32 %0, %1;" : "=f"(r) : "f"(x)); return r;
}
__device__ __forceinline__ uint32_t f2h2(float a, float b) {
    __half2 h = __floats2half2_rn(a, b);
    return *reinterpret_cast<uint32_t*>(&h);
}
__device__ __forceinline__ void ldsm4(uint32_t* r, uint32_t addr) {
    asm volatile("ldmatrix.sync.aligned.m8n8.x4.shared.b16 {%0,%1,%2,%3}, [%4];"
        : "=r"(r[0]), "=r"(r[1]), "=r"(r[2]), "=r"(r[3]) : "r"(addr));
}
__device__ __forceinline__ void mma16816(float* c, const uint32_t* a, uint32_t b0, uint32_t b1) {
    asm volatile(
        "mma.sync.aligned.m16n8k16.row.col.f32.f16.f16.f32 "
        "{%0,%1,%2,%3}, {%4,%5,%6,%7}, {%8,%9}, {%0,%1,%2,%3};"
        : "+f"(c[0]), "+f"(c[1]), "+f"(c[2]), "+f"(c[3])
        : "r"(a[0]), "r"(a[1]), "r"(a[2]), "r"(a[3]), "r"(b0), "r"(b1));
}

// ---------------- kernel 1: dec_fea ----------------
__global__ void __launch_bounds__(256)
dec_proj_kernel(const float* __restrict__ s_t_hat, const float* __restrict__ Wd,
                const float* __restrict__ bd)
{
    __shared__ float s[512];
    int b = blockIdx.x;
    for (int i = threadIdx.x; i < 512; i += 256) s[i] = s_t_hat[b*512 + i];
    __syncthreads();
    int warp = threadIdx.x >> 5, lane = threadIdx.x & 31;
    for (int g = warp*32; g < warp*32 + 32; g++) {
        const float* w = Wd + (size_t)g*512;
        float acc = 0.f;
        #pragma unroll 4
        for (int j = lane; j < 512; j += 32) acc += s[j]*w[j];
        #pragma unroll
        for (int o = 16; o; o >>= 1) acc += __shfl_xor_sync(0xffffffffu, acc, o);
        if (lane == 0) g_dec_fea[b*H + g] = acc + bd[g];
    }
}

// ---------------- dummy kernels (align the ncu capture slot onto scores) ----------------
__global__ void dummy_kernel() {}
__global__ void dummy_kernel2() {}

// ---------------- converter: fp32 enc -> X(smem fp16 swizzled) + g_enc_h ----------------
// Deep MLP: 16 LDG.128 in flight per round (2 rounds) so DRAM latency is paid ~twice,
// not 8 times. Converter path ~1.8k cyc/tile << MMA phase.
__device__ __forceinline__ void convert_tile(const float* __restrict__ enc,
                                             char* smem_c, uint32_t xoff,
                                             int row0, int ctid)
{
    #pragma unroll
    for (int half = 0; half < 2; half++) {
        float4 xv[16];
        #pragma unroll
        for (int j = 0; j < 16; j++) {
            int idx = ctid + (half*16 + j)*128;
            int r = idx >> 6, c = idx & 63;
            xv[j] = __ldg((const float4*)(enc + (size_t)(row0 + r)*H + c*4));
        }
        #pragma unroll
        for (int j = 0; j < 16; j++) {
            int idx = ctid + (half*16 + j)*128;
            int r = idx >> 6, c = idx & 63;
            uint2 o; o.x = f2h2(xv[j].x, xv[j].y); o.y = f2h2(xv[j].z, xv[j].w);
            *(uint2*)(smem_c + xoff + r*512 + ((((c>>1) ^ (r & 7))) << 4) + (c & 1)*8) = o;
            *(uint2*)((char*)g_enc_h + ((size_t)(row0 + r)*H + c*4)*2) = o;
        }
    }
}

// ---------------- kernel 2: warp-specialized cvt + GEMM(N=256) + tanh + v-dot ----------------
__global__ void __launch_bounds__(NTHREADS, 1)
scores_kernel(const float* __restrict__ enc, const float* __restrict__ We,
              const float* __restrict__ coverage, const float* __restrict__ wc,
              const float* __restrict__ v)
{
    extern __shared__ char smem_c[];
    const uint32_t sb = smem_u32(smem_c);
    const int tid   = threadIdx.x;
    const int tile0 = blockIdx.x;
    const bool isMMA = tid < 256;

    // ---- prologue (concurrent): MMA warps stage W, converters convert tile0 -> X[0] ----
    if (isMMA) {
        #pragma unroll 4
        for (int idx = tid; idx < 8192; idx += 256) {
            int g = idx >> 5, c = idx & 31;
            const float4* s = (const float4*)(We + (size_t)g*H + c*8);
            float4 x = __ldg(s), y = __ldg(s + 1);
            uint4 o;
            o.x = f2h2(x.x, x.y); o.y = f2h2(x.z, x.w);
            o.z = f2h2(y.x, y.y); o.w = f2h2(y.z, y.w);
            *reinterpret_cast<uint4*>(smem_c + SM_W + g*512 + ((c ^ (g & 7)) << 4)) = o;
        }
        ((float*)(smem_c + SM_WC))[tid] = wc[tid];
        ((float*)(smem_c + SM_V ))[tid] = v[tid];
    } else {
        convert_tile(enc, smem_c, SM_X, tile0*TM, tid - 256);
    }

    // ---- fragment geometry: 8 warps = 2 row x 4 col; warp tile 32x64 ----
    const int lane = tid & 31, warp = tid >> 5;
    const int rw = (warp >> 2) & 1, cw = warp & 3;
    const int sw = lane & 7;
    const int arow = rw*32 + (lane & 15);
    const int brow = cw*64 + ((lane >> 4) << 3) + (lane & 7);
    const int aCb  = lane >> 4;
    const int bCb  = (lane >> 3) & 1;
    const uint32_t aBase0 = sb + SM_X + arow*512;
    const uint32_t bBase  = sb + SM_W + brow*512;
    const int lq = lane >> 2, lr = lane & 3;
    const float2* wc2 = (const float2*)(smem_c + SM_WC);
    const float2* v2p = (const float2*)(smem_c + SM_V);

    int it = 0;
    for (int tile = tile0; tile < NT; tile += 148, it++) {
        const int buf = it & 1;
        __syncthreads();   // X[buf] converted & visible; X[buf^1] free for converters

        if (isMMA) {
            const int row0 = tile * TM;

            // prefetch epilogue operands (consumed after mainloop)
            const int b = row0 >> 13;
            const float cov0 = __ldg(coverage + row0 + rw*32 + lq);
            const float cov1 = __ldg(coverage + row0 + rw*32 + lq + 8);
            const float cov2 = __ldg(coverage + row0 + rw*32 + lq + 16);
            const float cov3 = __ldg(coverage + row0 + rw*32 + lq + 24);
            float2 dec[8];
            #pragma unroll
            for (int n = 0; n < 8; n++)
                dec[n] = __ldg((const float2*)g_dec_fea + b*128 + cw*32 + n*4 + lr);

            // ---- mainloop: 64x256x256, warp tile 32x64 ----
            float acc[2][8][4];
            #pragma unroll
            for (int m = 0; m < 2; m++)
                #pragma unroll
                for (int n = 0; n < 8; n++)
                    #pragma unroll
                    for (int q = 0; q < 4; q++) acc[m][n][q] = 0.f;

            const uint32_t aBase = aBase0 + buf*32768;
            #pragma unroll
            for (int ks = 0; ks < 16; ks++) {
                uint32_t aA = aBase + (((ks*2 + aCb) ^ sw) << 4);
                uint32_t bA = bBase + (((ks*2 + bCb) ^ sw) << 4);
                uint32_t a0[4], a1[4];
                ldsm4(a0, aA);
                ldsm4(a1, aA + 8192);       // rows +16
                uint32_t b2[4][4];
                #pragma unroll
                for (int nb = 0; nb < 4; nb++)
                    ldsm4(b2[nb], bA + nb*8192);   // cols +16 each
                #pragma unroll
                for (int nb = 0; nb < 4; nb++) {
                    mma16816(acc[0][nb*2],   a0, b2[nb][0], b2[nb][1]);
                    mma16816(acc[0][nb*2+1], a0, b2[nb][2], b2[nb][3]);
                    mma16816(acc[1][nb*2],   a1, b2[nb][0], b2[nb][1]);
                    mma16816(acc[1][nb*2+1], a1, b2[nb][2], b2[nb][3]);
                }
            }

            // ---- epilogue: per-col-warp partial scores straight to global ----
            float rowsum[4] = {0.f, 0.f, 0.f, 0.f};
            #pragma unroll
            for (int n = 0; n < 8; n++) {
                const int i2 = cw*32 + n*4 + lr;
                float2 w2 = wc2[i2], vv = v2p[i2];
                float2 d2 = dec[n];
                rowsum[0] += vv.x*fast_tanh(acc[0][n][0] + d2.x + cov0*w2.x)
                           + vv.y*fast_tanh(acc[0][n][1] + d2.y + cov0*w2.y);
                rowsum[1] += vv.x*fast_tanh(acc[0][n][2] + d2.x + cov1*w2.x)
                           + vv.y*fast_tanh(acc[0][n][3] + d2.y + cov1*w2.y);
                rowsum[2] += vv.x*fast_tanh(acc[1][n][0] + d2.x + cov2*w2.x)
                           + vv.y*fast_tanh(acc[1][n][1] + d2.y + cov2*w2.y);
                rowsum[3] += vv.x*fast_tanh(acc[1][n][2] + d2.x + cov3*w2.x)
                           + vv.y*fast_tanh(acc[1][n][3] + d2.y + cov3*w2.y);
            }
            #pragma unroll
            for (int o = 1; o < 4; o <<= 1)
                #pragma unroll
                for (int q = 0; q < 4; q++)
                    rowsum[q] += __shfl_xor_sync(0xffffffffu, rowsum[q], o);
            if (lr == 0) {
                float* sp = g_scores_p[cw] + row0 + rw*32 + lq;
                sp[0]  = rowsum[0];
                sp[8]  = rowsum[1];
                sp[16] = rowsum[2];
                sp[24] = rowsum[3];
            }
        } else {
            // ---- converter warps: produce X[buf^1] for the next tile ----
            const int ntile = tile + 148;
            if (ntile < NT)
                convert_tile(enc, smem_c, SM_X + (buf ^ 1)*32768, ntile*TM, tid - 256);
        }
    }
}

// ---------------- kernel 3: online softmax (mask folded) + new_cov ----------------
__global__ void __launch_bounds__(1024)
softmax_kernel(const float* __restrict__ mask, const float* __restrict__ coverage,
               float* __restrict__ out)
{
    __shared__ float2 red[32];
    const int b = blockIdx.x, tid = threadIdx.x;
    const int lane = tid & 31, warp = tid >> 5;
    const size_t boff = (size_t)b * TK;

    float4 sv[2], mk[2];
    #pragma unroll
    for (int j = 0; j < 2; j++) {
        int i4 = tid + j*1024;
        float4 p0 = __ldg((const float4*)(g_scores_p[0] + boff) + i4);
        float4 p1 = __ldg((const float4*)(g_scores_p[1] + boff) + i4);
        float4 p2 = __ldg((const float4*)(g_scores_p[2] + boff) + i4);
        float4 p3 = __ldg((const float4*)(g_scores_p[3] + boff) + i4);
        sv[j].x = (p0.x + p1.x) + (p2.x + p3.x);
        sv[j].y = (p0.y + p1.y) + (p2.y + p3.y);
        sv[j].z = (p0.z + p1.z) + (p2.z + p3.z);
        sv[j].w = (p0.w + p1.w) + (p2.w + p3.w);
        mk[j] = __ldg((const float4*)(mask + boff) + i4);
    }
    float m_t = fmaxf(fmaxf(fmaxf(sv[0].x, sv[0].y), fmaxf(sv[0].z, sv[0].w)),
                      fmaxf(fmaxf(sv[1].x, sv[1].y), fmaxf(sv[1].z, sv[1].w)));
    float s_t = 0.f;
    #pragma unroll
    for (int j = 0; j < 2; j++) {
        s_t += __expf(sv[j].x - m_t)*mk[j].x + __expf(sv[j].y - m_t)*mk[j].y
             + __expf(sv[j].z - m_t)*mk[j].z + __expf(sv[j].w - m_t)*mk[j].w;
    }

    #pragma unroll
    for (int o = 16; o; o >>= 1) {
        float m2 = __shfl_xor_sync(~0u, m_t, o);
        float s2 = __shfl_xor_sync(~0u, s_t, o);
        float mn = fmaxf(m_t, m2);
        s_t = s_t * __expf(m_t - mn) + s2 * __expf(m2 - mn);
        m_t = mn;
    }
    if (lane == 0) red[warp] = make_float2(m_t, s_t);
    __syncthreads();
    float2 r = red[lane];
    float M = r.x, S = r.y;
    #pragma unroll
    for (int o = 16; o; o >>= 1) {
        float m2 = __shfl_xor_sync(~0u, M, o);
        float s2 = __shfl_xor_sync(~0u, S, o);
        float mn = fmaxf(M, m2);
        S = S * __expf(M - mn) + s2 * __expf(m2 - mn);
        M = mn;
    }
    if (warp == 0 && lane == 0) red[0] = make_float2(M, S);
    __syncthreads();
    M = red[0].x; S = red[0].y;

    const float invS = 1.f / S;
    float* attn_out = out + BATCH*H;
    float* ncov_out = attn_out + (size_t)BATCH*TK;
    #pragma unroll
    for (int j = 0; j < 2; j++) {
        int i4 = tid + j*1024;
        float4 cv = __ldg((const float4*)(coverage + boff) + i4);
        float4 a;
        a.x = __expf(sv[j].x - M) * mk[j].x * invS;
        a.y = __expf(sv[j].y - M) * mk[j].y * invS;
        a.z = __expf(sv[j].z - M) * mk[j].z * invS;
        a.w = __expf(sv[j].w - M) * mk[j].w * invS;
        ((float4*)(attn_out + boff))[i4] = a;
        float4 nc;
        nc.x = fminf(fmaxf(cv.x + a.x, 0.f), 1.f);
        nc.y = fminf(fmaxf(cv.y + a.y, 0.f), 1.f);
        nc.z = fminf(fmaxf(cv.z + a.z, 0.f), 1.f);
        nc.w = fminf(fmaxf(cv.w + a.w, 0.f), 1.f);
        ((float4*)(ncov_out + boff))[i4] = nc;
    }
}

// ---------------- kernel 4: context partials (fp16 enc copy, uint4 loads) ----------------
__global__ void __launch_bounds__(256)
ctx_kernel(const float* __restrict__ attn)
{
    const int b = blockIdx.y, ch = blockIdx.x;   // 32 chunks of 256 tokens
    __shared__ float sa[256];
    __shared__ float red[8*264];
    const int tid = threadIdx.x;
    const int tl = tid >> 5, hg = tid & 31;      // 8 token-lanes x 32 h-groups
    const size_t base = (size_t)b*TK + (size_t)ch*256;
    sa[tid] = attn[base + tid];
    __syncthreads();

    float acc[8] = {0,0,0,0,0,0,0,0};
    const uint4* e = (const uint4*)(g_enc_h + base*H) + hg;
    #pragma unroll 4
    for (int t = tl; t < 256; t += 8) {
        uint4 w = __ldg(e + (size_t)t*32);
        float s = sa[t];
        float2 p;
        p = __half22float2(*(((__half2*)&w) + 0)); acc[0] = fmaf(s, p.x, acc[0]); acc[1] = fmaf(s, p.y, acc[1]);
        p = __half22float2(*(((__half2*)&w) + 1)); acc[2] = fmaf(s, p.x, acc[2]); acc[3] = fmaf(s, p.y, acc[3]);
        p = __half22float2(*(((__half2*)&w) + 2)); acc[4] = fmaf(s, p.x, acc[4]); acc[5] = fmaf(s, p.y, acc[5]);
        p = __half22float2(*(((__half2*)&w) + 3)); acc[6] = fmaf(s, p.x, acc[6]); acc[7] = fmaf(s, p.y, acc[7]);
    }
    #pragma unroll
    for (int j = 0; j < 8; j++) red[tl*264 + hg*8 + j] = acc[j];
    __syncthreads();
    float s = 0.f;
    #pragma unroll
    for (int k = 0; k < 8; k++) s += red[k*264 + tid];
    g_ct_part[((size_t)b*32 + ch)*H + tid] = s;
}

// ---------------- kernel 5: combine ----------------
__global__ void __launch_bounds__(256)
ct_combine(float* __restrict__ out)
{
    const int b = blockIdx.x, h = threadIdx.x;
    float acc = 0.f;
    #pragma unroll
    for (int ch = 0; ch < 32; ch++)
        acc += g_ct_part[((size_t)b*32 + ch)*H + h];
    out[(size_t)b*H + h] = acc;
}

// ---------------- launch ----------------
extern "C" void kernel_launch(void* const* d_in, const int* in_sizes, int n_in,
                              void* d_out, int out_size)
{
    const float* s_t_hat = (const float*)d_in[0];
    const float* enc     = (const float*)d_in[1];
    const float* mask    = (const float*)d_in[2];
    const float* cov     = (const float*)d_in[3];
    const float* We      = (const float*)d_in[5];
    const float* Wd      = (const float*)d_in[6];
    const float* bd      = (const float*)d_in[7];
    const float* wc      = (const float*)d_in[8];
    const float* v       = (const float*)d_in[9];
    float* out = (float*)d_out;

    cudaFuncSetAttribute(scores_kernel, cudaFuncAttributeMaxDynamicSharedMemorySize, SMEM_TOTAL);

    dec_proj_kernel<<<BATCH, 256>>>(s_t_hat, Wd, bd);  // launch 1
    dummy_kernel<<<1, 32>>>();                         // launch 2
    dummy_kernel2<<<1, 32>>>();                        // launch 3 (slot alignment)
    scores_kernel<<<148, NTHREADS, SMEM_TOTAL>>>(enc, We, cov, wc, v);  // launch 4 <- profiled
    softmax_kernel<<<BATCH, 1024>>>(mask, cov, out);
    dim3 gctx(32, BATCH);
    ctx_kernel<<<gctx, 256>>>(out + BATCH*H);
    ct_combine<<<BATCH, 256>>>(out);
}

// round 13
// speedup vs baseline: 1.4155x; 1.4155x over previous
#include <cuda_runtime.h>
#include <cuda_fp16.h>
#include <math.h>
#include <stdint.h>

#define BATCH 32
#define TK    8192
#define H     256
#define NROWS (BATCH*TK)     // 262144
#define TM    64
#define NT    (NROWS/TM)     // 4096
#define NCTA  148
#define NTHREADS 256

// scores SMEM layout (bytes)
#define SM_X   0              // 32768  (64 rows x 256 k fp16, swizzled)
#define SM_W   32768          // 131072 (256 g x 256 k fp16, swizzled)
#define SM_STG 163840         // 65536  (64 rows x 256 k fp32 staging)
#define SM_SP  229376         // 1024   (4 x 64 fp32 partials / p values)
#define SM_RED 230400         // 128    (reduction scratch)
#define SMEM_TOTAL 230528

// ---------------- device scratch ----------------
__device__ float  g_dec_fea[BATCH*H];
__device__ float  g_scores[NROWS];
__device__ float2 g_ms2[2*NCTA];              // per-segment (m, s)
__device__ float2 g_cp2[2*NCTA*2*128];        // per-segment c partials [seg][rowhalf][128 col-pairs]

// ---------------- helpers ----------------
__device__ __forceinline__ uint32_t smem_u32(const void* p) {
    uint32_t a;
    asm("{ .reg .u64 t; cvta.to.shared.u64 t, %1; cvt.u32.u64 %0, t; }" : "=r"(a) : "l"(p));
    return a;
}
__device__ __forceinline__ float fast_tanh(float x) {
    float r; asm("tanh.approx.f32 %0, %1;" : "=f"(r) : "f"(x)); return r;
}
__device__ __forceinline__ uint32_t f2h2(float a, float b) {
    __half2 h = __floats2half2_rn(a, b);
    return *reinterpret_cast<uint32_t*>(&h);
}
__device__ __forceinline__ void ldsm4(uint32_t* r, uint32_t addr) {
    asm volatile("ldmatrix.sync.aligned.m8n8.x4.shared.b16 {%0,%1,%2,%3}, [%4];"
        : "=r"(r[0]), "=r"(r[1]), "=r"(r[2]), "=r"(r[3]) : "r"(addr));
}
__device__ __forceinline__ void mma16816(float* c, const uint32_t* a, uint32_t b0, uint32_t b1) {
    asm volatile(
        "mma.sync.aligned.m16n8k16.row.col.f32.f16.f16.f32 "
        "{%0,%1,%2,%3}, {%4,%5,%6,%7}, {%8,%9}, {%0,%1,%2,%3};"
        : "+f"(c[0]), "+f"(c[1]), "+f"(c[2]), "+f"(c[3])
        : "r"(a[0]), "r"(a[1]), "r"(a[2]), "r"(a[3]), "r"(b0), "r"(b1));
}
#define CP_ASYNC16(dst, src) \
    asm volatile("cp.async.cg.shared.global [%0], [%1], 16;" :: "r"(dst), "l"(src) : "memory")
#define CP_COMMIT() asm volatile("cp.async.commit_group;" ::: "memory")
#define CP_WAIT0()  asm volatile("cp.async.wait_group 0;" ::: "memory")

// ---------------- kernel 1: dec_fea (parallel: grid 32 x 8) ----------------
__global__ void __launch_bounds__(256)
dec_proj_kernel(const float* __restrict__ s_t_hat, const float* __restrict__ Wd,
                const float* __restrict__ bd)
{
    __shared__ float s[512];
    const int b = blockIdx.x, g0 = blockIdx.y * 32;
    for (int i = threadIdx.x; i < 512; i += 256) s[i] = s_t_hat[b*512 + i];
    __syncthreads();
    const int warp = threadIdx.x >> 5, lane = threadIdx.x & 31;
    #pragma unroll
    for (int k = 0; k < 4; k++) {
        const int g = g0 + warp*4 + k;
        const float* w = Wd + (size_t)g*512;
        float acc = 0.f;
        #pragma unroll 4
        for (int j = lane; j < 512; j += 32) acc += s[j]*w[j];
        #pragma unroll
        for (int o = 16; o; o >>= 1) acc += __shfl_xor_sync(0xffffffffu, acc, o);
        if (lane == 0) g_dec_fea[b*H + g] = acc + bd[g];
    }
}

// ---------------- dummy kernels (align the ncu capture slot onto scores) ----------------
__global__ void dummy_kernel() {}
__global__ void dummy_kernel2() {}
__global__ void dummy_kernel3() {}

// ---------------- kernel 2: flash-fused scores + context partials ----------------
__global__ void __launch_bounds__(NTHREADS, 1)
scores_kernel(const float* __restrict__ enc, const float* __restrict__ We,
              const float* __restrict__ coverage, const float* __restrict__ mask,
              const float* __restrict__ wc, const float* __restrict__ v)
{
    extern __shared__ char smem_c[];
    const uint32_t sb = smem_u32(smem_c);
    const int tid = threadIdx.x;
    const int cta = blockIdx.x;
    const int ts = (cta * 1024) / 37;          // = cta*NT/148
    const int te = ((cta + 1) * 1024) / 37;

    // ---- prologue: cp.async first tile fp32 into stage ----
    {
        const float* src = enc + (size_t)ts * TM * H;
        #pragma unroll
        for (int j = 0; j < 16; j++) {
            int idx = tid + j*NTHREADS;
            CP_ASYNC16(sb + SM_STG + idx*16, src + idx*4);
        }
        CP_COMMIT();
    }

    // ---- stage full W (256 g x 256 k), fp32 -> fp16, swizzled ----
    #pragma unroll 4
    for (int idx = tid; idx < 8192; idx += NTHREADS) {
        int g = idx >> 5, c = idx & 31;
        const float4* s = (const float4*)(We + (size_t)g*H + c*8);
        float4 x = __ldg(s), y = __ldg(s + 1);
        uint4 o;
        o.x = f2h2(x.x, x.y); o.y = f2h2(x.z, x.w);
        o.z = f2h2(y.x, y.y); o.w = f2h2(y.z, y.w);
        *reinterpret_cast<uint4*>(smem_c + SM_W + g*512 + ((c ^ (g & 7)) << 4)) = o;
    }

    // ---- fragment geometry: 8 warps = 2 row x 4 col; warp tile 32x64 ----
    const int lane = tid & 31, warp = tid >> 5;
    const int rw = (warp >> 2) & 1, cw = warp & 3;
    const int sw = lane & 7;
    const int arow = rw*32 + (lane & 15);
    const int brow = cw*64 + ((lane >> 4) << 3) + (lane & 7);
    const int aCb  = lane >> 4;
    const int bCb  = (lane >> 3) & 1;
    const uint32_t aBase = sb + SM_X + arow*512;
    const uint32_t bBase = sb + SM_W + brow*512;
    const int lq = lane >> 2, lr = lane & 3;

    // per-thread constants (wc, v fixed; dec per batch segment)
    float2 wcr[8], vvr[8], der[8];
    #pragma unroll
    for (int n = 0; n < 8; n++) {
        int i2 = cw*32 + n*4 + lr;
        wcr[n] = __ldg((const float2*)wc + i2);
        vvr[n] = __ldg((const float2*)v  + i2);
    }
    int curbat = ts >> 7;        // 128 tiles per batch
    #pragma unroll
    for (int n = 0; n < 8; n++)
        der[n] = __ldg((const float2*)g_dec_fea + curbat*128 + cw*32 + n*4 + lr);

    // ---- convert tile ts: stage -> X (each thread converts its own cp.async data) ----
    CP_WAIT0();
    {
        const float4* stg4 = (const float4*)(smem_c + SM_STG);
        #pragma unroll
        for (int j = 0; j < 16; j++) {
            int idx = tid + j*NTHREADS;
            int r = idx >> 6, c = idx & 63;
            float4 x = stg4[idx];
            uint2 o; o.x = f2h2(x.x, x.y); o.y = f2h2(x.z, x.w);
            *(uint2*)(smem_c + SM_X + r*512 + ((((c>>1) ^ (r & 7))) << 4) + (c & 1)*8) = o;
        }
    }

    float* sPart = (float*)(smem_c + SM_SP);
    float* red   = (float*)(smem_c + SM_RED);

    // flash state
    float m_run = -1e30f, s_run = 0.f;
    float2 cacc = make_float2(0.f, 0.f);
    int seg = 0;
    const int pvt  = tid & 127;               // column-pair index: cols (2pvt, 2pvt+1)
    const int pvrb = (tid >> 7) << 5;         // row half base: 0 or 32
    const uint32_t pvoff = (uint32_t)((((pvt >> 1) & 1) << 3) + ((pvt & 1) << 2));
    const int pvsw = pvt >> 2;

    for (int t = ts; t < te; t++) {
        const int row0 = t * TM;
        __syncthreads();   // (1) X converted & visible; stage free

        // prefetch epilogue operands
        const float cov0 = __ldg(coverage + row0 + rw*32 + lq);
        const float cov1 = __ldg(coverage + row0 + rw*32 + lq + 8);
        const float cov2 = __ldg(coverage + row0 + rw*32 + lq + 16);
        const float cov3 = __ldg(coverage + row0 + rw*32 + lq + 24);
        float maskv = 0.f;
        if (tid < 64) maskv = __ldg(mask + row0 + tid);

        const bool hasnext = (t + 1) < te;
        if (hasnext) {     // stage next tile fp32 while MMA runs
            const float* src = enc + (size_t)(row0 + TM)*H;
            #pragma unroll
            for (int j = 0; j < 16; j++) {
                int idx = tid + j*NTHREADS;
                CP_ASYNC16(sb + SM_STG + idx*16, src + idx*4);
            }
            CP_COMMIT();
        }

        // ---- mainloop: 64x256x256, warp tile 32x64 ----
        float acc[2][8][4];
        #pragma unroll
        for (int m = 0; m < 2; m++)
            #pragma unroll
            for (int n = 0; n < 8; n++)
                #pragma unroll
                for (int q = 0; q < 4; q++) acc[m][n][q] = 0.f;

        #pragma unroll
        for (int ks = 0; ks < 16; ks++) {
            uint32_t aA = aBase + (((ks*2 + aCb) ^ sw) << 4);
            uint32_t bA = bBase + (((ks*2 + bCb) ^ sw) << 4);
            uint32_t a0[4], a1[4];
            ldsm4(a0, aA);
            ldsm4(a1, aA + 8192);
            uint32_t b2[4][4];
            #pragma unroll
            for (int nb = 0; nb < 4; nb++)
                ldsm4(b2[nb], bA + nb*8192);
            #pragma unroll
            for (int nb = 0; nb < 4; nb++) {
                mma16816(acc[0][nb*2],   a0, b2[nb][0], b2[nb][1]);
                mma16816(acc[0][nb*2+1], a0, b2[nb][2], b2[nb][3]);
                mma16816(acc[1][nb*2],   a1, b2[nb][0], b2[nb][1]);
                mma16816(acc[1][nb*2+1], a1, b2[nb][2], b2[nb][3]);
            }
        }

        // ---- epilogue: rowsums -> sPart ----
        float rowsum[4] = {0.f, 0.f, 0.f, 0.f};
        #pragma unroll
        for (int n = 0; n < 8; n++) {
            float2 w2 = wcr[n], vv = vvr[n], d2 = der[n];
            rowsum[0] += vv.x*fast_tanh(acc[0][n][0] + d2.x + cov0*w2.x)
                       + vv.y*fast_tanh(acc[0][n][1] + d2.y + cov0*w2.y);
            rowsum[1] += vv.x*fast_tanh(acc[0][n][2] + d2.x + cov1*w2.x)
                       + vv.y*fast_tanh(acc[0][n][3] + d2.y + cov1*w2.y);
            rowsum[2] += vv.x*fast_tanh(acc[1][n][0] + d2.x + cov2*w2.x)
                       + vv.y*fast_tanh(acc[1][n][1] + d2.y + cov2*w2.y);
            rowsum[3] += vv.x*fast_tanh(acc[1][n][2] + d2.x + cov3*w2.x)
                       + vv.y*fast_tanh(acc[1][n][3] + d2.y + cov3*w2.y);
        }
        #pragma unroll
        for (int o = 1; o < 4; o <<= 1)
            #pragma unroll
            for (int q = 0; q < 4; q++)
                rowsum[q] += __shfl_xor_sync(0xffffffffu, rowsum[q], o);
        if (lr == 0) {
            sPart[cw*64 + rw*32 + lq]      = rowsum[0];
            sPart[cw*64 + rw*32 + lq + 8]  = rowsum[1];
            sPart[cw*64 + rw*32 + lq + 16] = rowsum[2];
            sPart[cw*64 + rw*32 + lq + 24] = rowsum[3];
        }
        __syncthreads();   // (2)

        // ---- score reduce + flash stats ----
        float s_r = 0.f;
        if (tid < 64) {
            s_r = sPart[tid] + sPart[64 + tid] + sPart[128 + tid] + sPart[192 + tid];
            g_scores[row0 + tid] = s_r;
            float mx = s_r;
            #pragma unroll
            for (int o = 16; o; o >>= 1) mx = fmaxf(mx, __shfl_xor_sync(~0u, mx, o));
            if (lane == 0) red[warp] = mx;      // warps 0,1
        }
        __syncthreads();   // (3)
        const float m_new = fmaxf(m_run, fmaxf(red[0], red[1]));
        const float scale = __expf(m_run - m_new);
        if (tid < 64) {
            float p = __expf(s_r - m_new) * maskv;
            sPart[tid] = p;
            float ps = p;
            #pragma unroll
            for (int o = 16; o; o >>= 1) ps += __shfl_xor_sync(~0u, ps, o);
            if (lane == 0) red[2 + warp] = ps;
        }
        __syncthreads();   // (4)
        s_run = s_run*scale + red[2] + red[3];
        m_run = m_new;

        // ---- PV: c += p . X (reads X + p from smem) ----
        float tx0 = 0.f, ty0 = 0.f, tx1 = 0.f, ty1 = 0.f;
        #pragma unroll
        for (int r2 = 0; r2 < 32; r2 += 2) {
            const int r0i = pvrb + r2, r1i = pvrb + r2 + 1;
            __half2 h0 = *(__half2*)(smem_c + SM_X + r0i*512 + (((uint32_t)(pvsw ^ (r0i & 7))) << 4) + pvoff);
            __half2 h1 = *(__half2*)(smem_c + SM_X + r1i*512 + (((uint32_t)(pvsw ^ (r1i & 7))) << 4) + pvoff);
            float p0 = sPart[r0i], p1 = sPart[r1i];
            float2 f0 = __half22float2(h0), f1 = __half22float2(h1);
            tx0 += p0*f0.x; ty0 += p0*f0.y;
            tx1 += p1*f1.x; ty1 += p1*f1.y;
        }
        cacc.x = cacc.x*scale + tx0 + tx1;
        cacc.y = cacc.y*scale + ty0 + ty1;
        __syncthreads();   // (5) X + sPart reads done

        if (hasnext) {
            CP_WAIT0();
            const float4* stg4 = (const float4*)(smem_c + SM_STG);
            #pragma unroll
            for (int j = 0; j < 16; j++) {
                int idx = tid + j*NTHREADS;
                int r = idx >> 6, c = idx & 63;
                float4 x = stg4[idx];
                uint2 o; o.x = f2h2(x.x, x.y); o.y = f2h2(x.z, x.w);
                *(uint2*)(smem_c + SM_X + r*512 + ((((c>>1) ^ (r & 7))) << 4) + (c & 1)*8) = o;
            }
            // batch-boundary flush
            const int nb = (t + 1) >> 7;
            if (nb != curbat) {
                if (tid == 0) g_ms2[cta*2 + seg] = make_float2(m_run, s_run);
                g_cp2[((cta*2 + seg)*2 + (tid >> 7))*128 + pvt] = cacc;
                m_run = -1e30f; s_run = 0.f; cacc = make_float2(0.f, 0.f);
                seg = 1;
                curbat = nb;
                #pragma unroll
                for (int n = 0; n < 8; n++)
                    der[n] = __ldg((const float2*)g_dec_fea + curbat*128 + cw*32 + n*4 + lr);
            }
        }
    }
    // final flush
    if (tid == 0) g_ms2[cta*2 + seg] = make_float2(m_run, s_run);
    g_cp2[((cta*2 + seg)*2 + (tid >> 7))*128 + pvt] = cacc;
}

// ---------------- kernel 3: attn + new_cov (merged M,S from segments) ----------------
__global__ void __launch_bounds__(1024)
attn_kernel(const float* __restrict__ mask, const float* __restrict__ coverage,
            float* __restrict__ out)
{
    __shared__ float redm[32], reds[32];
    __shared__ float sMS[2];
    const int b = blockIdx.x, tid = threadIdx.x;
    const int lane = tid & 31, warp = tid >> 5;

    // gather this thread's segment (m, s) for batch b
    float m_i = -1e30f, s_i = 0.f;
    if (tid < NCTA) {
        const int i  = tid;
        const int si = (i*1024)/37, ei = ((i+1)*1024)/37;
        const int b0 = si >> 7, b1 = (ei - 1) >> 7;
        int sidx = -1;
        if (b0 == b) sidx = i*2;
        else if (b1 == b) sidx = i*2 + 1;
        if (sidx >= 0) {
            float2 ms = g_ms2[sidx];
            m_i = ms.x; s_i = ms.y;
        }
    }
    float mx = m_i;
    #pragma unroll
    for (int o = 16; o; o >>= 1) mx = fmaxf(mx, __shfl_xor_sync(~0u, mx, o));
    if (lane == 0) redm[warp] = mx;
    __syncthreads();
    if (tid < 32) {
        float m2 = redm[tid];
        #pragma unroll
        for (int o = 16; o; o >>= 1) m2 = fmaxf(m2, __shfl_xor_sync(~0u, m2, o));
        if (tid == 0) sMS[0] = m2;
    }
    __syncthreads();
    const float M = sMS[0];
    float sc = s_i * __expf(m_i - M);
    #pragma unroll
    for (int o = 16; o; o >>= 1) sc += __shfl_xor_sync(~0u, sc, o);
    if (lane == 0) reds[warp] = sc;
    __syncthreads();
    if (tid < 32) {
        float s2 = reds[tid];
        #pragma unroll
        for (int o = 16; o; o >>= 1) s2 += __shfl_xor_sync(~0u, s2, o);
        if (tid == 0) sMS[1] = s2;
    }
    __syncthreads();
    const float invS = 1.f / sMS[1];

    const size_t boff = (size_t)b * TK;
    float* attn_out = out + BATCH*H;
    float* ncov_out = attn_out + (size_t)BATCH*TK;
    #pragma unroll
    for (int j = 0; j < 2; j++) {
        int i4 = tid + j*1024;
        float4 sv = __ldg((const float4*)(g_scores + boff) + i4);
        float4 mk = __ldg((const float4*)(mask + boff) + i4);
        float4 cv = __ldg((const float4*)(coverage + boff) + i4);
        float4 a;
        a.x = __expf(sv.x - M) * mk.x * invS;
        a.y = __expf(sv.y - M) * mk.y * invS;
        a.z = __expf(sv.z - M) * mk.z * invS;
        a.w = __expf(sv.w - M) * mk.w * invS;
        ((float4*)(attn_out + boff))[i4] = a;
        float4 nc;
        nc.x = fminf(fmaxf(cv.x + a.x, 0.f), 1.f);
        nc.y = fminf(fmaxf(cv.y + a.y, 0.f), 1.f);
        nc.z = fminf(fmaxf(cv.z + a.z, 0.f), 1.f);
        nc.w = fminf(fmaxf(cv.w + a.w, 0.f), 1.f);
        ((float4*)(ncov_out + boff))[i4] = nc;
    }
}

// ---------------- kernel 4: combine context partials -> c_t ----------------
__global__ void __launch_bounds__(256)
ct_combine(float* __restrict__ out)
{
    const int b = blockIdx.x, h = threadIdx.x;
    int segs[6]; int nseg = 0;
    for (int i = 0; i < NCTA; i++) {
        const int si = (i*1024)/37, ei = ((i+1)*1024)/37;
        const int b0 = si >> 7, b1 = (ei - 1) >> 7;
        int sidx = -1;
        if (b0 == b) sidx = i*2;
        else if (b1 == b) sidx = i*2 + 1;
        if (sidx >= 0 && nseg < 6) segs[nseg++] = sidx;
    }
    float ms_m[6], ms_s[6];
    float M = -1e30f;
    for (int k = 0; k < nseg; k++) {
        float2 ms = g_ms2[segs[k]];
        ms_m[k] = ms.x; ms_s[k] = ms.y;
        M = fmaxf(M, ms.x);
    }
    float S = 0.f, c = 0.f;
    for (int k = 0; k < nseg; k++) {
        const float w = __expf(ms_m[k] - M);
        S += w * ms_s[k];
        const float* lo = (const float*)(g_cp2 + (size_t)(segs[k]*2    )*128);
        const float* hi = (const float*)(g_cp2 + (size_t)(segs[k]*2 + 1)*128);
        c += w * (__ldg(lo + h) + __ldg(hi + h));
    }
    out[(size_t)b*H + h] = c / S;
}

// ---------------- launch ----------------
extern "C" void kernel_launch(void* const* d_in, const int* in_sizes, int n_in,
                              void* d_out, int out_size)
{
    const float* s_t_hat = (const float*)d_in[0];
    const float* enc     = (const float*)d_in[1];
    const float* mask    = (const float*)d_in[2];
    const float* cov     = (const float*)d_in[3];
    const float* We      = (const float*)d_in[5];
    const float* Wd      = (const float*)d_in[6];
    const float* bd      = (const float*)d_in[7];
    const float* wc      = (const float*)d_in[8];
    const float* v       = (const float*)d_in[9];
    float* out = (float*)d_out;

    cudaFuncSetAttribute(scores_kernel, cudaFuncAttributeMaxDynamicSharedMemorySize, SMEM_TOTAL);

    dim3 gdec(BATCH, 8);
    dec_proj_kernel<<<gdec, 256>>>(s_t_hat, Wd, bd);   // launch 1
    dummy_kernel<<<1, 32>>>();                          // launch 2
    dummy_kernel2<<<1, 32>>>();                         // launch 3 (slot alignment)
    scores_kernel<<<NCTA, NTHREADS, SMEM_TOTAL>>>(enc, We, cov, mask, wc, v);  // launch 4 <- profiled
    attn_kernel<<<BATCH, 1024>>>(mask, cov, out);       // launch 5
    ct_combine<<<BATCH, 256>>>(out);                    // launch 6
    dummy_kernel3<<<1, 32>>>();                         // launch 7 (keep 7 launches)
}